// round 15
// baseline (speedup 1.0000x reference)
#include <cuda_runtime.h>
#include <cstdint>

#define NB 16
#define CI 64
#define CHB 9216     // floats per chunk weight block: 9*16*64

// ---------------- device scratch (no allocs allowed) ----------------
// g_up layout: [b][y][c][x]  (y=256, c=64, x=256) -> coalesced pre stores
__device__ float g_up[(size_t)NB * 256 * CI * 256];
__device__ float g_x [(size_t)NB * CI * 128 * 128];     // [b][c][h][w], tf32-rounded
__device__ float g_wpre [4 * 4 * CHB];                  // [mt][chunk][t][kp][n']
__device__ float g_wpost[4 * CHB];                      // [chunk][t][kp][n']

__device__ __forceinline__ uint32_t tf32r(float x) {
    uint32_t r; asm("cvt.rna.tf32.f32 %0, %1;" : "=r"(r) : "f"(x)); return r;
}
__device__ __forceinline__ float tf32f(float x) { return __uint_as_float(tf32r(x)); }

__device__ __forceinline__ uint32_t smem_u32(const void* p) {
    uint32_t a;
    asm("{ .reg .u64 t; cvta.to.shared.u64 t, %1; cvt.u32.u64 %0, t; }" : "=r"(a) : "l"(p));
    return a;
}
// L1-bypassing 16B async copy: A tiles are stream-once, keep L1 for B
__device__ __forceinline__ void cp16(uint32_t dst, const void* src, uint32_t sz) {
    asm volatile("cp.async.cg.shared.global [%0], [%1], 16, %2;"
                 :: "r"(dst), "l"(src), "r"(sz) : "memory");
}
__device__ __forceinline__ void cp4(uint32_t dst, const void* src, uint32_t sz) {
    asm volatile("cp.async.ca.shared.global [%0], [%1], 4, %2;"
                 :: "r"(dst), "l"(src), "r"(sz) : "memory");
}
#define CP_COMMIT() asm volatile("cp.async.commit_group;" ::: "memory")
#define CP_WAIT0()  asm volatile("cp.async.wait_group 0;" ::: "memory")

// m16n8k8 tf32 MMA, fp32 accumulate (sm_80+ baseline -> tensor pipe)
__device__ __forceinline__ void mma8(float* c, const uint32_t a[4],
                                     uint32_t b0, uint32_t b1) {
    asm volatile(
        "mma.sync.aligned.m16n8k8.row.col.f32.tf32.tf32.f32 "
        "{%0,%1,%2,%3}, {%4,%5,%6,%7}, {%8,%9}, {%0,%1,%2,%3};"
        : "+f"(c[0]), "+f"(c[1]), "+f"(c[2]), "+f"(c[3])
        : "r"(a[0]), "r"(a[1]), "r"(a[2]), "r"(a[3]), "r"(b0), "r"(b1));
}

// inverse of n-permutation n' = (n&7)*4 + ((n>>3)&3) + (n>>5)*32
__device__ __forceinline__ int inv_perm64(int np) {
    return (np >> 5) * 32 + (np & 3) * 8 + ((np & 31) >> 2);
}

// ---------------- prep kernels ----------------
__global__ void round_x(const float* __restrict__ x, int n) {
    int i = blockIdx.x * blockDim.x + threadIdx.x;
    if (i < n) g_x[i] = tf32f(x[i]);
}
__global__ void reorder_pre(const float* __restrict__ w) {
    int o = blockIdx.x * blockDim.x + threadIdx.x;
    if (o >= 16 * CHB) return;
    int np = o & 63;
    int kp = (o >> 6) & 15;
    int t  = (o >> 10) % 9;
    int c  = (o / (9 * 16 * 64)) & 3;
    int mt = o / (4 * 9 * 16 * 64);
    int R  = mt * 64 + inv_perm64(np);
    int ch = (R & 3) * 64 + (R >> 2);
    g_wpre[o] = tf32f(w[((ch * 64 + c * 16 + kp) * 3 + t / 3) * 3 + (t % 3)]);
}
__global__ void reorder_post(const float* __restrict__ w) {
    int o = blockIdx.x * blockDim.x + threadIdx.x;
    if (o >= 4 * CHB) return;
    int np = o & 63;
    int kp = (o >> 6) & 15;
    int t  = (o >> 10) % 9;
    int c  = o / (9 * 16 * 64);
    int co = inv_perm64(np);
    g_wpost[o] = tf32f(w[((co * 64 + c * 16 + kp) * 3 + t / 3) * 3 + (t % 3)]);
}

// ---------------------------------------------------------------------------
// Implicit-GEMM conv, warp mma.sync tf32, 128-thread CTAs (4 warps), each
// warp 64 px (mf=4) x 64 ch (nf=8). Block = 2 image rows x 128 px.
// Double-buffered cp.async (L1-bypass) A staging; B via LDG.128 (L1-resident).
// A window: p = (gw - px0) + 4; p=3 and p=132 are window borders.
// STRIDE mod 32 == 8 -> fragment banks conflict-free.
// ---------------------------------------------------------------------------
#define STRIDE 136
#define LINES  64                       // 4 rows x 16 cins
#define BUFN   (LINES * STRIDE)         // floats per buffer
#define SMEMB  (2 * BUFN * 4)           // 69632 B

template<int W, int H, bool WAVELET>
__global__ __launch_bounds__(128, 2)
void conv_mma(const float* __restrict__ bias, float* __restrict__ outp)
{
    extern __shared__ float smem[];
    const uint32_t sb = smem_u32(smem);

    const int tid  = threadIdx.x;
    const int lane = tid & 31;
    const int wid  = tid >> 5;              // 0..3
    const int gr   = lane >> 2;
    const int ct   = lane & 3;
    const int wm     = wid & 1;             // 64-px segment within window
    const int rowsel = wid >> 1;            // image row within block

    const int h0  = 2 * blockIdx.x;
    const int b   = blockIdx.y;
    const int z   = blockIdx.z;
    const int px0 = WAVELET ? 0 : z * 128;  // window start
    const int mt  = WAVELET ? z : 0;

    const float* wsrc = WAVELET ? (g_wpre + (size_t)mt * 4 * CHB) : g_wpost;

    const int sline0 = tid >> 5;            // 4 lines per pass (128/32)
    const int sc4    = tid & 31;

    // source line address for (cc, ci, gh):
    //   pre : g_x  [b][c][h][w]       -> ((b*64 + c)*128 + gh)*128
    //   post: g_up [b][y][c][x]       -> ((b*256 + gh)*64 + c)*256
    auto src_line = [&](int cc, int ci, int gh) -> const float* {
        if (WAVELET)
            return g_x + ((size_t)(b * CI + cc * 16 + ci) * H + gh) * W;
        else
            return g_up + ((size_t)(b * 256 + gh) * CI + cc * 16 + ci) * 256;
    };

    // stage chunk cc into buffer bf (interior via cp16, borders via cp4)
    auto stage = [&](int cc, int bf) {
        const uint32_t dbuf = sb + (uint32_t)bf * (BUFN * 4u);
        #pragma unroll
        for (int pass = 0; pass < 16; ++pass) {
            const int line = pass * 4 + sline0;
            const int r  = line >> 4;
            const int ci = line & 15;
            const int gh = h0 - 1 + r;
            const bool hok = (gh >= 0) && (gh < H);
            const float* sp = src_line(cc, ci, hok ? gh : 0) + px0;
            cp16(dbuf + (uint32_t)(line * STRIDE + 4 + sc4 * 4) * 4u,
                 sp + sc4 * 4, hok ? 16u : 0u);
        }
        // borders: tid<64 -> p=3 (gw=px0-1); tid>=64 -> p=132 (gw=px0+128)
        {
            const int line = tid & 63;
            const int r  = line >> 4;
            const int ci = line & 15;
            const int gh = h0 - 1 + r;
            const int gw = (tid < 64) ? (px0 - 1) : (px0 + 128);
            const int p  = (tid < 64) ? 3 : 132;
            const bool ok = (gh >= 0) && (gh < H) && (gw >= 0) && (gw < W);
            cp4(dbuf + (uint32_t)(line * STRIDE + p) * 4u,
                src_line(cc, ci, ok ? gh : 0) + (ok ? gw : 0),
                ok ? 4u : 0u);
        }
    };

    float acc[4][8][4];
    #pragma unroll
    for (int mf = 0; mf < 4; ++mf)
        #pragma unroll
        for (int j = 0; j < 8; ++j)
            #pragma unroll
            for (int u = 0; u < 4; ++u) acc[mf][j][u] = 0.0f;

    stage(0, 0);
    CP_COMMIT();

    for (int cc = 0; cc < 4; ++cc) {
        CP_WAIT0();
        __syncthreads();
        if (cc < 3) { stage(cc + 1, (cc + 1) & 1); CP_COMMIT(); }

        const float*  sIn = smem + (cc & 1) * BUFN;
        const float4* wb  = (const float4*)(wsrc + (size_t)cc * CHB);

        // ---- compute: 9 taps x 2 k-halves x 32 MMAs ----
        #pragma unroll
        for (int t = 0; t < 9; ++t) {
            const int rr  = rowsel + t / 3;
            const int dwp = t % 3;
            #pragma unroll
            for (int ks = 0; ks < 2; ++ks) {
                const int kb = ks * 8;
                const int l0i = (t * 16 + kb + ct) * 16 + gr;
                const int l4i = (t * 16 + kb + ct + 4) * 16 + gr;
                float4 B0[2], B1[2];
                B0[0] = __ldg(&wb[l0i]);
                B0[1] = __ldg(&wb[l0i + 8]);
                B1[0] = __ldg(&wb[l4i]);
                B1[1] = __ldg(&wb[l4i + 8]);

                uint32_t a[4][4];
                #pragma unroll
                for (int mf = 0; mf < 4; ++mf) {
                    const int px = wm * 64 + mf * 16 + gr + dwp + 3;
                    const float* l0 = &sIn[(rr * 16 + kb + ct) * STRIDE];
                    const float* l4 = &sIn[(rr * 16 + kb + ct + 4) * STRIDE];
                    a[mf][0] = __float_as_uint(l0[px]);
                    a[mf][1] = __float_as_uint(l0[px + 8]);
                    a[mf][2] = __float_as_uint(l4[px]);
                    a[mf][3] = __float_as_uint(l4[px + 8]);
                }
                #pragma unroll
                for (int j = 0; j < 8; ++j) {
                    const float4& v0 = B0[j >> 2];
                    const float4& v1 = B1[j >> 2];
                    float f0 = (j & 2) ? ((j & 1) ? v0.w : v0.z)
                                       : ((j & 1) ? v0.y : v0.x);
                    float f1 = (j & 2) ? ((j & 1) ? v1.w : v1.z)
                                       : ((j & 1) ? v1.y : v1.x);
                    #pragma unroll
                    for (int mf = 0; mf < 4; ++mf)
                        mma8(acc[mf][j], a[mf],
                             __float_as_uint(f0), __float_as_uint(f1));
                }
            }
        }
    }

    // ------------------------- epilogue -------------------------
    if (WAVELET) {
        const int h = h0 + rowsel;
        const bool lower = (ct & 1) == 0;        // holds (ll,lh); else (hl,hh)
        #pragma unroll
        for (int mf = 0; mf < 4; ++mf) {
            #pragma unroll
            for (int half = 0; half < 2; ++half) {
                const int m = wm * 64 + mf * 16 + gr + half * 8;
                #pragma unroll
                for (int j = 0; j < 8; ++j) {
                    const int colb = j * 8 + 2 * ct;
                    const int q = mt * 16 + (colb >> 2);
                    float v0 = acc[mf][j][half * 2 + 0] + __ldg(&bias[(lower ? 0 : 128) + q]);
                    float v1 = acc[mf][j][half * 2 + 1] + __ldg(&bias[(lower ? 64 : 192) + q]);
                    float s = v0 + v1, d = v0 - v1;
                    float so = __shfl_xor_sync(0xffffffffu, s, 1);
                    float dd = __shfl_xor_sync(0xffffffffu, d, 1);
                    float r0, r1;
                    int yy;
                    if (lower) { r0 = 0.5f * (s + so);  r1 = 0.5f * (d + dd);  yy = 2 * h; }
                    else       { r0 = 0.5f * (so - s);  r1 = 0.5f * (dd - d);  yy = 2 * h + 1; }
                    // g_up [b][y][c][x]
                    float* dst = g_up + ((size_t)(b * 256 + yy) * CI + q) * 256 + 2 * m;
                    *(float2*)dst = make_float2(tf32f(r0), tf32f(r1));   // pre-rounded for post
                }
            }
        }
    } else {
        const int h = h0 + rowsel;
        #pragma unroll
        for (int mf = 0; mf < 4; ++mf) {
            #pragma unroll
            for (int half = 0; half < 2; ++half) {
                const int x = px0 + wm * 64 + mf * 16 + gr + half * 8;
                #pragma unroll
                for (int j = 0; j < 8; ++j) {
                    const int ch = j * 8 + 2 * ct;
                    outp[((size_t)(b * CI + ch) * 256 + h) * 256 + x] =
                        acc[mf][j][half * 2 + 0] + __ldg(&bias[ch]);
                    outp[((size_t)(b * CI + ch + 1) * 256 + h) * 256 + x] =
                        acc[mf][j][half * 2 + 1] + __ldg(&bias[ch + 1]);
                }
            }
        }
    }
}

extern "C" void kernel_launch(void* const* d_in, const int* in_sizes, int n_in,
                              void* d_out, int out_size)
{
    (void)in_sizes; (void)n_in; (void)out_size;
    const float* x      = (const float*)d_in[0];
    const float* w_pre  = (const float*)d_in[1];
    const float* b_pre  = (const float*)d_in[2];
    const float* w_post = (const float*)d_in[3];
    const float* b_post = (const float*)d_in[4];
    float* out = (float*)d_out;

    static int attr_done = 0;
    if (!attr_done) {
        cudaFuncSetAttribute(conv_mma<128, 128, true>,
                             cudaFuncAttributeMaxDynamicSharedMemorySize, SMEMB);
        cudaFuncSetAttribute(conv_mma<256, 256, false>,
                             cudaFuncAttributeMaxDynamicSharedMemorySize, SMEMB);
        attr_done = 1;
    }

    const int nx = NB * CI * 128 * 128;
    round_x<<<(nx + 255) / 256, 256>>>(x, nx);
    reorder_pre <<<(16 * CHB + 255) / 256, 256>>>(w_pre);
    reorder_post<<<(4 * CHB + 255) / 256, 256>>>(w_post);

    // conv_pre + wavelet -> g_up : 2 rows x 128 px per block, 4 n-tiles in z
    conv_mma<128, 128, true>
        <<<dim3(64, NB, 4), 128, SMEMB>>>(b_pre, nullptr);
    // conv_post : 2 rows x 128 px per block, window halves in z
    conv_mma<256, 256, false>
        <<<dim3(128, NB, 2), 128, SMEMB>>>(b_post, out);
}

// round 16
// speedup vs baseline: 1.0918x; 1.0918x over previous
#include <cuda_runtime.h>
#include <cstdint>

#define NB 16
#define CI 64
#define CHB 9216     // floats per chunk weight block: 9*16*64

// ---------------- device scratch (no allocs allowed) ----------------
__device__ float g_up[(size_t)NB * CI * 256 * 256];     // [b][c][y][x], tf32-rounded
__device__ float g_x [(size_t)NB * CI * 128 * 128];     // [b][c][h][w], tf32-rounded
__device__ float g_wpre [4 * 4 * CHB];                  // [mt][chunk][t][kp][n']
__device__ float g_wpost[4 * CHB];                      // [chunk][t][kp][n']

__device__ __forceinline__ uint32_t tf32r(float x) {
    uint32_t r; asm("cvt.rna.tf32.f32 %0, %1;" : "=r"(r) : "f"(x)); return r;
}
__device__ __forceinline__ float tf32f(float x) { return __uint_as_float(tf32r(x)); }

__device__ __forceinline__ uint32_t smem_u32(const void* p) {
    uint32_t a;
    asm("{ .reg .u64 t; cvta.to.shared.u64 t, %1; cvt.u32.u64 %0, t; }" : "=r"(a) : "l"(p));
    return a;
}
__device__ __forceinline__ void cp16(uint32_t dst, const void* src, uint32_t sz) {
    asm volatile("cp.async.ca.shared.global [%0], [%1], 16, %2;"
                 :: "r"(dst), "l"(src), "r"(sz) : "memory");
}
#define CP_COMMIT() asm volatile("cp.async.commit_group;" ::: "memory")
#define CP_WAIT0()  asm volatile("cp.async.wait_group 0;" ::: "memory")

// m16n8k8 tf32 MMA, fp32 accumulate (sm_80+ baseline -> tensor pipe)
__device__ __forceinline__ void mma8(float* c, const uint32_t a[4],
                                     uint32_t b0, uint32_t b1) {
    asm volatile(
        "mma.sync.aligned.m16n8k8.row.col.f32.tf32.tf32.f32 "
        "{%0,%1,%2,%3}, {%4,%5,%6,%7}, {%8,%9}, {%0,%1,%2,%3};"
        : "+f"(c[0]), "+f"(c[1]), "+f"(c[2]), "+f"(c[3])
        : "r"(a[0]), "r"(a[1]), "r"(a[2]), "r"(a[3]), "r"(b0), "r"(b1));
}

// inverse of n-permutation n' = (n&7)*4 + ((n>>3)&3) + (n>>5)*32
__device__ __forceinline__ int inv_perm64(int np) {
    return (np >> 5) * 32 + (np & 3) * 8 + ((np & 31) >> 2);
}

// ---------------- prep kernels ----------------
__global__ void round_x(const float* __restrict__ x, int n) {
    int i = blockIdx.x * blockDim.x + threadIdx.x;
    if (i < n) g_x[i] = tf32f(x[i]);
}
__global__ void reorder_pre(const float* __restrict__ w) {
    int o = blockIdx.x * blockDim.x + threadIdx.x;
    if (o >= 16 * CHB) return;
    int np = o & 63;
    int kp = (o >> 6) & 15;
    int t  = (o >> 10) % 9;
    int c  = (o / (9 * 16 * 64)) & 3;
    int mt = o / (4 * 9 * 16 * 64);
    int R  = mt * 64 + inv_perm64(np);
    int ch = (R & 3) * 64 + (R >> 2);
    g_wpre[o] = tf32f(w[((ch * 64 + c * 16 + kp) * 3 + t / 3) * 3 + (t % 3)]);
}
__global__ void reorder_post(const float* __restrict__ w) {
    int o = blockIdx.x * blockDim.x + threadIdx.x;
    if (o >= 4 * CHB) return;
    int np = o & 63;
    int kp = (o >> 6) & 15;
    int t  = (o >> 10) % 9;
    int c  = o / (9 * 16 * 64);
    int co = inv_perm64(np);
    g_wpost[o] = tf32f(w[((co * 64 + c * 16 + kp) * 3 + t / 3) * 3 + (t % 3)]);
}

// ---------------------------------------------------------------------------
// Implicit-GEMM conv, warp mma.sync tf32, 128-thread CTAs (4 warps), each
// warp 64 px (mf=4) x 64 ch (nf=8). Block = 2 image rows x 128 px.
// A: double-buffered cp.async staging. B: staged per chunk into smem once
// per CTA, mainloop reads via LDS.128 (29 cyc vs L2's 234).
// A window: p = (gw - px0) + 4; p=3 and p=132 are window borders.
// A STRIDE mod 32 == 8 -> fragment banks conflict-free.
// B stride 72: float-bank = 8ct+4gr+c -> each LDS.128 phase conflict-free.
// ---------------------------------------------------------------------------
#define STRIDE 136
#define LINES  64                       // 4 rows x 16 cins
#define BUFN   (LINES * STRIDE)         // floats per A buffer (8704)
#define BSTR   72                       // B smem line stride (floats)
#define BOFFF  (2 * BUFN)               // B region float offset
#define SMEMB  ((2 * BUFN + 144 * BSTR) * 4)   // 111104 B

template<int W, int H, bool WAVELET>
__global__ __launch_bounds__(128, 2)
void conv_mma(const float* __restrict__ bias, float* __restrict__ outp)
{
    extern __shared__ float smem[];
    const uint32_t sb = smem_u32(smem);

    const int tid  = threadIdx.x;
    const int lane = tid & 31;
    const int wid  = tid >> 5;              // 0..3
    const int gr   = lane >> 2;
    const int ct   = lane & 3;
    const int wm     = wid & 1;             // 64-px segment within window
    const int rowsel = wid >> 1;            // image row within block

    const int h0  = 2 * blockIdx.x;
    const int b   = blockIdx.y;
    const int z   = blockIdx.z;
    const int px0 = WAVELET ? 0 : z * 128;  // window start
    const int mt  = WAVELET ? z : 0;

    const float* src  = WAVELET ? g_x : g_up;
    const float* wsrc = WAVELET ? (g_wpre + (size_t)mt * 4 * CHB) : g_wpost;

    const int sline0 = tid >> 5;            // 4 lines per pass (128/32)
    const int sc4    = tid & 31;

    // stage A chunk cc into buffer bf (interior cp.async, borders scalar)
    auto stageA = [&](int cc, int bf) {
        const uint32_t dbuf = sb + (uint32_t)bf * (BUFN * 4u);
        #pragma unroll
        for (int pass = 0; pass < 16; ++pass) {
            const int line = pass * 4 + sline0;
            const int r  = line >> 4;
            const int ci = line & 15;
            const int gh = h0 - 1 + r;
            const bool hok = (gh >= 0) && (gh < H);
            const int ghc = hok ? gh : 0;
            const float* sp = src + ((size_t)(b * CI + cc * 16 + ci) * H + ghc) * W + px0;
            cp16(dbuf + (uint32_t)(line * STRIDE + 4 + sc4 * 4) * 4u,
                 sp + sc4 * 4, hok ? 16u : 0u);
        }
        // borders: tid<64 -> p=3 (gw=px0-1); tid>=64 -> p=132 (gw=px0+128)
        {
            const int line = tid & 63;
            const int r  = line >> 4;
            const int ci = line & 15;
            const int gh = h0 - 1 + r;
            const int gw = (tid < 64) ? (px0 - 1) : (px0 + 128);
            const int p  = (tid < 64) ? 3 : 132;
            float v = 0.0f;
            if (gh >= 0 && gh < H && gw >= 0 && gw < W)
                v = __ldg(&src[((size_t)(b * CI + cc * 16 + ci) * H + gh) * W + gw]);
            smem[bf * BUFN + line * STRIDE + p] = v;
        }
    };

    // stage B chunk cc into smem (once per CTA; 2304 float4 / 128 thr = 18)
    auto stageB = [&](int cc) {
        const uint32_t dB = sb + (uint32_t)BOFFF * 4u;
        const float* wp = wsrc + (size_t)cc * CHB;
        #pragma unroll
        for (int s = 0; s < 18; ++s) {
            const int idx4 = s * 128 + tid;      // 0..2303
            const int line = idx4 >> 4;          // 0..143
            const int np4  = idx4 & 15;
            cp16(dB + (uint32_t)(line * BSTR + np4 * 4) * 4u,
                 wp + idx4 * 4, 16u);
        }
    };

    float acc[4][8][4];
    #pragma unroll
    for (int mf = 0; mf < 4; ++mf)
        #pragma unroll
        for (int j = 0; j < 8; ++j)
            #pragma unroll
            for (int u = 0; u < 4; ++u) acc[mf][j][u] = 0.0f;

    stageA(0, 0);
    CP_COMMIT();

    for (int cc = 0; cc < 4; ++cc) {
        if (cc) __syncthreads();             // all warps done reading B(cc-1)
        stageB(cc);
        CP_COMMIT();
        CP_WAIT0();                          // A(cc) + B(cc) arrived
        __syncthreads();
        if (cc < 3) { stageA(cc + 1, (cc + 1) & 1); CP_COMMIT(); }

        const float* sIn = smem + (cc & 1) * BUFN;
        const float* sB  = smem + BOFFF;

        // ---- compute: 9 taps x 2 k-halves x 32 MMAs ----
        #pragma unroll
        for (int t = 0; t < 9; ++t) {
            const int rr  = rowsel + t / 3;
            const int dwp = t % 3;
            #pragma unroll
            for (int ks = 0; ks < 2; ++ks) {
                const int kb = ks * 8;
                // B: 4 x LDS.128 (conflict-free), lines ct and ct+4
                const float* bl0 = &sB[(t * 16 + kb + ct) * BSTR + gr * 4];
                const float* bl1 = &sB[(t * 16 + kb + ct + 4) * BSTR + gr * 4];
                float4 B0[2], B1[2];
                B0[0] = *(const float4*)&bl0[0];
                B0[1] = *(const float4*)&bl0[32];
                B1[0] = *(const float4*)&bl1[0];
                B1[1] = *(const float4*)&bl1[32];

                uint32_t a[4][4];
                #pragma unroll
                for (int mf = 0; mf < 4; ++mf) {
                    const int px = wm * 64 + mf * 16 + gr + dwp + 3;
                    const float* l0 = &sIn[(rr * 16 + kb + ct) * STRIDE];
                    const float* l4 = &sIn[(rr * 16 + kb + ct + 4) * STRIDE];
                    a[mf][0] = __float_as_uint(l0[px]);
                    a[mf][1] = __float_as_uint(l0[px + 8]);
                    a[mf][2] = __float_as_uint(l4[px]);
                    a[mf][3] = __float_as_uint(l4[px + 8]);
                }
                #pragma unroll
                for (int j = 0; j < 8; ++j) {
                    const float4& v0 = B0[j >> 2];
                    const float4& v1 = B1[j >> 2];
                    float f0 = (j & 2) ? ((j & 1) ? v0.w : v0.z)
                                       : ((j & 1) ? v0.y : v0.x);
                    float f1 = (j & 2) ? ((j & 1) ? v1.w : v1.z)
                                       : ((j & 1) ? v1.y : v1.x);
                    #pragma unroll
                    for (int mf = 0; mf < 4; ++mf)
                        mma8(acc[mf][j], a[mf],
                             __float_as_uint(f0), __float_as_uint(f1));
                }
            }
        }
    }

    // ------------------------- epilogue -------------------------
    if (WAVELET) {
        const int h = h0 + rowsel;
        const bool lower = (ct & 1) == 0;        // holds (ll,lh); else (hl,hh)
        #pragma unroll
        for (int mf = 0; mf < 4; ++mf) {
            #pragma unroll
            for (int half = 0; half < 2; ++half) {
                const int m = wm * 64 + mf * 16 + gr + half * 8;
                #pragma unroll
                for (int j = 0; j < 8; ++j) {
                    const int colb = j * 8 + 2 * ct;
                    const int q = mt * 16 + (colb >> 2);
                    float v0 = acc[mf][j][half * 2 + 0] + __ldg(&bias[(lower ? 0 : 128) + q]);
                    float v1 = acc[mf][j][half * 2 + 1] + __ldg(&bias[(lower ? 64 : 192) + q]);
                    float s = v0 + v1, d = v0 - v1;
                    float so = __shfl_xor_sync(0xffffffffu, s, 1);
                    float dd = __shfl_xor_sync(0xffffffffu, d, 1);
                    float r0, r1;
                    int yy;
                    if (lower) { r0 = 0.5f * (s + so);  r1 = 0.5f * (d + dd);  yy = 2 * h; }
                    else       { r0 = 0.5f * (so - s);  r1 = 0.5f * (dd - d);  yy = 2 * h + 1; }
                    float* dst = g_up + (((size_t)b * CI + q) * 256 + yy) * 256 + 2 * m;
                    *(float2*)dst = make_float2(tf32f(r0), tf32f(r1));   // pre-rounded for post
                }
            }
        }
    } else {
        const int h = h0 + rowsel;
        #pragma unroll
        for (int mf = 0; mf < 4; ++mf) {
            #pragma unroll
            for (int half = 0; half < 2; ++half) {
                const int x = px0 + wm * 64 + mf * 16 + gr + half * 8;
                #pragma unroll
                for (int j = 0; j < 8; ++j) {
                    const int ch = j * 8 + 2 * ct;
                    outp[((size_t)(b * CI + ch) * 256 + h) * 256 + x] =
                        acc[mf][j][half * 2 + 0] + __ldg(&bias[ch]);
                    outp[((size_t)(b * CI + ch + 1) * 256 + h) * 256 + x] =
                        acc[mf][j][half * 2 + 1] + __ldg(&bias[ch + 1]);
                }
            }
        }
    }
}

extern "C" void kernel_launch(void* const* d_in, const int* in_sizes, int n_in,
                              void* d_out, int out_size)
{
    (void)in_sizes; (void)n_in; (void)out_size;
    const float* x      = (const float*)d_in[0];
    const float* w_pre  = (const float*)d_in[1];
    const float* b_pre  = (const float*)d_in[2];
    const float* w_post = (const float*)d_in[3];
    const float* b_post = (const float*)d_in[4];
    float* out = (float*)d_out;

    static int attr_done = 0;
    if (!attr_done) {
        cudaFuncSetAttribute(conv_mma<128, 128, true>,
                             cudaFuncAttributeMaxDynamicSharedMemorySize, SMEMB);
        cudaFuncSetAttribute(conv_mma<256, 256, false>,
                             cudaFuncAttributeMaxDynamicSharedMemorySize, SMEMB);
        attr_done = 1;
    }

    const int nx = NB * CI * 128 * 128;
    round_x<<<(nx + 255) / 256, 256>>>(x, nx);
    reorder_pre <<<(16 * CHB + 255) / 256, 256>>>(w_pre);
    reorder_post<<<(4 * CHB + 255) / 256, 256>>>(w_post);

    // conv_pre + wavelet -> g_up : 2 rows x 128 px per block, 4 n-tiles in z
    conv_mma<128, 128, true>
        <<<dim3(64, NB, 4), 128, SMEMB>>>(b_pre, nullptr);
    // conv_post : 2 rows x 128 px per block, window halves in z
    conv_mma<256, 256, false>
        <<<dim3(128, NB, 2), 128, SMEMB>>>(b_post, out);
}

// round 17
// speedup vs baseline: 1.1185x; 1.0244x over previous
#include <cuda_runtime.h>
#include <cstdint>

#define NB 16
#define CI 64
#define CHB 9216     // floats per chunk weight block: 9*16*64

// ---------------- device scratch (no allocs allowed) ----------------
__device__ float g_up[(size_t)NB * CI * 256 * 256];     // [b][c][y][x], tf32-rounded
__device__ float g_x [(size_t)NB * CI * 128 * 128];     // [b][c][h][w], tf32-rounded
__device__ float g_wpre [4 * 4 * CHB];                  // [mt][chunk][t][kp][n']
__device__ float g_wpost[4 * CHB];                      // [chunk][t][kp][n']

__device__ __forceinline__ uint32_t tf32r(float x) {
    uint32_t r; asm("cvt.rna.tf32.f32 %0, %1;" : "=r"(r) : "f"(x)); return r;
}
__device__ __forceinline__ float tf32f(float x) { return __uint_as_float(tf32r(x)); }

__device__ __forceinline__ uint32_t smem_u32(const void* p) {
    uint32_t a;
    asm("{ .reg .u64 t; cvta.to.shared.u64 t, %1; cvt.u32.u64 %0, t; }" : "=r"(a) : "l"(p));
    return a;
}
__device__ __forceinline__ void cp16(uint32_t dst, const void* src, uint32_t sz) {
    asm volatile("cp.async.ca.shared.global [%0], [%1], 16, %2;"
                 :: "r"(dst), "l"(src), "r"(sz) : "memory");
}
#define CP_COMMIT() asm volatile("cp.async.commit_group;" ::: "memory")
#define CP_WAIT0()  asm volatile("cp.async.wait_group 0;" ::: "memory")

// m16n8k8 tf32 MMA, fp32 accumulate (sm_80+ baseline -> tensor pipe)
__device__ __forceinline__ void mma8(float* c, const uint32_t a[4],
                                     uint32_t b0, uint32_t b1) {
    asm volatile(
        "mma.sync.aligned.m16n8k8.row.col.f32.tf32.tf32.f32 "
        "{%0,%1,%2,%3}, {%4,%5,%6,%7}, {%8,%9}, {%0,%1,%2,%3};"
        : "+f"(c[0]), "+f"(c[1]), "+f"(c[2]), "+f"(c[3])
        : "r"(a[0]), "r"(a[1]), "r"(a[2]), "r"(a[3]), "r"(b0), "r"(b1));
}

// inverse of n-permutation n' = (n&7)*4 + ((n>>3)&3) + (n>>5)*32
__device__ __forceinline__ int inv_perm64(int np) {
    return (np >> 5) * 32 + (np & 3) * 8 + ((np & 31) >> 2);
}

// ---------------- prep kernels ----------------
__global__ void round_x(const float* __restrict__ x, int n) {
    int i = blockIdx.x * blockDim.x + threadIdx.x;
    if (i < n) g_x[i] = tf32f(x[i]);
}
__global__ void reorder_pre(const float* __restrict__ w) {
    int o = blockIdx.x * blockDim.x + threadIdx.x;
    if (o >= 16 * CHB) return;
    int np = o & 63;
    int kp = (o >> 6) & 15;
    int t  = (o >> 10) % 9;
    int c  = (o / (9 * 16 * 64)) & 3;
    int mt = o / (4 * 9 * 16 * 64);
    int R  = mt * 64 + inv_perm64(np);
    int ch = (R & 3) * 64 + (R >> 2);
    g_wpre[o] = tf32f(w[((ch * 64 + c * 16 + kp) * 3 + t / 3) * 3 + (t % 3)]);
}
__global__ void reorder_post(const float* __restrict__ w) {
    int o = blockIdx.x * blockDim.x + threadIdx.x;
    if (o >= 4 * CHB) return;
    int np = o & 63;
    int kp = (o >> 6) & 15;
    int t  = (o >> 10) % 9;
    int c  = o / (9 * 16 * 64);
    int co = inv_perm64(np);
    g_wpost[o] = tf32f(w[((co * 64 + c * 16 + kp) * 3 + t / 3) * 3 + (t % 3)]);
}

// ---------------------------------------------------------------------------
// Implicit-GEMM conv, warp mma.sync tf32. 256-thread CTAs (8 warps), each
// warp 32 px (mf=2) x 64 ch (nf=8). Block = 2 image rows x 128 px.
// A: double-buffered cp.async staging. B: per-chunk smem tile, LDS.128.
// A window: p = (gw - px0) + 4; p=3 and p=132 are window borders.
// A STRIDE mod 32 == 8 -> fragment banks conflict-free.
// B stride 72: float-bank = 8ct+4gr+c -> each LDS.128 phase conflict-free.
// ---------------------------------------------------------------------------
#define STRIDE 136
#define LINES  64                       // 4 rows x 16 cins
#define BUFN   (LINES * STRIDE)         // floats per A buffer (8704)
#define BSTR   72                       // B smem line stride (floats)
#define BOFFF  (2 * BUFN)               // B region float offset
#define SMEMB  ((2 * BUFN + 144 * BSTR) * 4)   // 111104 B

template<int W, int H, bool WAVELET>
__global__ __launch_bounds__(256, 2)
void conv_mma(const float* __restrict__ bias, float* __restrict__ outp)
{
    extern __shared__ float smem[];
    const uint32_t sb = smem_u32(smem);

    const int tid  = threadIdx.x;
    const int lane = tid & 31;
    const int wid  = tid >> 5;              // 0..7
    const int gr   = lane >> 2;
    const int ct   = lane & 3;
    const int wm     = wid & 3;             // 32-px segment within window
    const int rowsel = wid >> 2;            // image row within block

    const int h0  = 2 * blockIdx.x;
    const int b   = blockIdx.y;
    const int z   = blockIdx.z;
    const int px0 = WAVELET ? 0 : z * 128;  // window start
    const int mt  = WAVELET ? z : 0;

    const float* src  = WAVELET ? g_x : g_up;
    const float* wsrc = WAVELET ? (g_wpre + (size_t)mt * 4 * CHB) : g_wpost;

    const int sline0 = tid >> 5;            // 8 lines per pass (256/32)
    const int sc4    = tid & 31;

    // stage A chunk cc into buffer bf (interior cp.async, borders scalar)
    auto stageA = [&](int cc, int bf) {
        const uint32_t dbuf = sb + (uint32_t)bf * (BUFN * 4u);
        #pragma unroll
        for (int pass = 0; pass < 8; ++pass) {
            const int line = pass * 8 + sline0;
            const int r  = line >> 4;
            const int ci = line & 15;
            const int gh = h0 - 1 + r;
            const bool hok = (gh >= 0) && (gh < H);
            const int ghc = hok ? gh : 0;
            const float* sp = src + ((size_t)(b * CI + cc * 16 + ci) * H + ghc) * W + px0;
            cp16(dbuf + (uint32_t)(line * STRIDE + 4 + sc4 * 4) * 4u,
                 sp + sc4 * 4, hok ? 16u : 0u);
        }
        // borders: tid<64 -> p=3 (gw=px0-1); tid in [64,128) -> p=132
        if (tid < 128) {
            const int line = tid & 63;
            const int r  = line >> 4;
            const int ci = line & 15;
            const int gh = h0 - 1 + r;
            const int gw = (tid < 64) ? (px0 - 1) : (px0 + 128);
            const int p  = (tid < 64) ? 3 : 132;
            float v = 0.0f;
            if (gh >= 0 && gh < H && gw >= 0 && gw < W)
                v = __ldg(&src[((size_t)(b * CI + cc * 16 + ci) * H + gh) * W + gw]);
            smem[bf * BUFN + line * STRIDE + p] = v;
        }
    };

    // stage B chunk cc into smem (2304 float4 / 256 thr = 9 per thread)
    auto stageB = [&](int cc) {
        const uint32_t dB = sb + (uint32_t)BOFFF * 4u;
        const float* wp = wsrc + (size_t)cc * CHB;
        #pragma unroll
        for (int s = 0; s < 9; ++s) {
            const int idx4 = s * 256 + tid;      // 0..2303
            const int line = idx4 >> 4;          // 0..143
            const int np4  = idx4 & 15;
            cp16(dB + (uint32_t)(line * BSTR + np4 * 4) * 4u,
                 wp + idx4 * 4, 16u);
        }
    };

    float acc[2][8][4];
    #pragma unroll
    for (int mf = 0; mf < 2; ++mf)
        #pragma unroll
        for (int j = 0; j < 8; ++j)
            #pragma unroll
            for (int u = 0; u < 4; ++u) acc[mf][j][u] = 0.0f;

    stageA(0, 0);
    CP_COMMIT();

    for (int cc = 0; cc < 4; ++cc) {
        if (cc) __syncthreads();             // all warps done reading B(cc-1)
        stageB(cc);
        CP_COMMIT();
        CP_WAIT0();                          // A(cc) + B(cc) arrived
        __syncthreads();
        if (cc < 3) { stageA(cc + 1, (cc + 1) & 1); CP_COMMIT(); }

        const float* sIn = smem + (cc & 1) * BUFN;
        const float* sB  = smem + BOFFF;

        // ---- compute: 9 taps x 2 k-halves x 16 MMAs ----
        #pragma unroll
        for (int t = 0; t < 9; ++t) {
            const int rr  = rowsel + t / 3;
            const int dwp = t % 3;
            #pragma unroll
            for (int ks = 0; ks < 2; ++ks) {
                const int kb = ks * 8;
                // B: 4 x LDS.128 (conflict-free), lines ct and ct+4
                const float* bl0 = &sB[(t * 16 + kb + ct) * BSTR + gr * 4];
                const float* bl1 = &sB[(t * 16 + kb + ct + 4) * BSTR + gr * 4];
                float4 B0[2], B1[2];
                B0[0] = *(const float4*)&bl0[0];
                B0[1] = *(const float4*)&bl0[32];
                B1[0] = *(const float4*)&bl1[0];
                B1[1] = *(const float4*)&bl1[32];

                uint32_t a[2][4];
                #pragma unroll
                for (int mf = 0; mf < 2; ++mf) {
                    const int px = wm * 32 + mf * 16 + gr + dwp + 3;
                    const float* l0 = &sIn[(rr * 16 + kb + ct) * STRIDE];
                    const float* l4 = &sIn[(rr * 16 + kb + ct + 4) * STRIDE];
                    a[mf][0] = __float_as_uint(l0[px]);
                    a[mf][1] = __float_as_uint(l0[px + 8]);
                    a[mf][2] = __float_as_uint(l4[px]);
                    a[mf][3] = __float_as_uint(l4[px + 8]);
                }
                #pragma unroll
                for (int j = 0; j < 8; ++j) {
                    const float4& v0 = B0[j >> 2];
                    const float4& v1 = B1[j >> 2];
                    float f0 = (j & 2) ? ((j & 1) ? v0.w : v0.z)
                                       : ((j & 1) ? v0.y : v0.x);
                    float f1 = (j & 2) ? ((j & 1) ? v1.w : v1.z)
                                       : ((j & 1) ? v1.y : v1.x);
                    #pragma unroll
                    for (int mf = 0; mf < 2; ++mf)
                        mma8(acc[mf][j], a[mf],
                             __float_as_uint(f0), __float_as_uint(f1));
                }
            }
        }
    }

    // ------------------------- epilogue -------------------------
    if (WAVELET) {
        const int h = h0 + rowsel;
        const bool lower = (ct & 1) == 0;        // holds (ll,lh); else (hl,hh)
        #pragma unroll
        for (int mf = 0; mf < 2; ++mf) {
            #pragma unroll
            for (int half = 0; half < 2; ++half) {
                const int m = wm * 32 + mf * 16 + gr + half * 8;
                #pragma unroll
                for (int j = 0; j < 8; ++j) {
                    const int colb = j * 8 + 2 * ct;
                    const int q = mt * 16 + (colb >> 2);
                    float v0 = acc[mf][j][half * 2 + 0] + __ldg(&bias[(lower ? 0 : 128) + q]);
                    float v1 = acc[mf][j][half * 2 + 1] + __ldg(&bias[(lower ? 64 : 192) + q]);
                    float s = v0 + v1, d = v0 - v1;
                    float so = __shfl_xor_sync(0xffffffffu, s, 1);
                    float dd = __shfl_xor_sync(0xffffffffu, d, 1);
                    float r0, r1;
                    int yy;
                    if (lower) { r0 = 0.5f * (s + so);  r1 = 0.5f * (d + dd);  yy = 2 * h; }
                    else       { r0 = 0.5f * (so - s);  r1 = 0.5f * (dd - d);  yy = 2 * h + 1; }
                    float* dst = g_up + (((size_t)b * CI + q) * 256 + yy) * 256 + 2 * m;
                    *(float2*)dst = make_float2(tf32f(r0), tf32f(r1));   // pre-rounded for post
                }
            }
        }
    } else {
        const int h = h0 + rowsel;
        #pragma unroll
        for (int mf = 0; mf < 2; ++mf) {
            #pragma unroll
            for (int half = 0; half < 2; ++half) {
                const int x = px0 + wm * 32 + mf * 16 + gr + half * 8;
                #pragma unroll
                for (int j = 0; j < 8; ++j) {
                    const int ch = j * 8 + 2 * ct;
                    outp[((size_t)(b * CI + ch) * 256 + h) * 256 + x] =
                        acc[mf][j][half * 2 + 0] + __ldg(&bias[ch]);
                    outp[((size_t)(b * CI + ch + 1) * 256 + h) * 256 + x] =
                        acc[mf][j][half * 2 + 1] + __ldg(&bias[ch + 1]);
                }
            }
        }
    }
}

extern "C" void kernel_launch(void* const* d_in, const int* in_sizes, int n_in,
                              void* d_out, int out_size)
{
    (void)in_sizes; (void)n_in; (void)out_size;
    const float* x      = (const float*)d_in[0];
    const float* w_pre  = (const float*)d_in[1];
    const float* b_pre  = (const float*)d_in[2];
    const float* w_post = (const float*)d_in[3];
    const float* b_post = (const float*)d_in[4];
    float* out = (float*)d_out;

    static int attr_done = 0;
    if (!attr_done) {
        cudaFuncSetAttribute(conv_mma<128, 128, true>,
                             cudaFuncAttributeMaxDynamicSharedMemorySize, SMEMB);
        cudaFuncSetAttribute(conv_mma<256, 256, false>,
                             cudaFuncAttributeMaxDynamicSharedMemorySize, SMEMB);
        attr_done = 1;
    }

    const int nx = NB * CI * 128 * 128;
    round_x<<<(nx + 255) / 256, 256>>>(x, nx);
    reorder_pre <<<(16 * CHB + 255) / 256, 256>>>(w_pre);
    reorder_post<<<(4 * CHB + 255) / 256, 256>>>(w_post);

    // conv_pre + wavelet -> g_up : 2 rows x 128 px per block, 4 n-tiles in z
    conv_mma<128, 128, true>
        <<<dim3(64, NB, 4), 256, SMEMB>>>(b_pre, nullptr);
    // conv_post : 2 rows x 128 px per block, window halves in z
    conv_mma<256, 256, false>
        <<<dim3(128, NB, 2), 256, SMEMB>>>(b_post, out);
}